// round 1
// baseline (speedup 1.0000x reference)
#include <cuda_runtime.h>
#include <math.h>

// ---------------------------------------------------------------------------
// Problem constants: B=8, N=256, T=128, D=256, H=8, hd=32, TOPK=32
// ---------------------------------------------------------------------------
#define BATCH 8
#define NN    256
#define TT    128
#define DD    256
#define HH    8
#define HD    32
#define TOPK  32

#define BN    (BATCH*NN)            // 2048
#define M_BIG ((size_t)BATCH*NN*TT) // 262144 rows for big GEMMs

// Scratch (device globals; allocation-free kernel_launch)
__device__ float g_q[BN*DD];                 // 2 MB
__device__ float g_k[BN*DD];                 // 2 MB
__device__ float g_attn[(size_t)BATCH*HH*NN*NN];   // 16 MB
__device__ float g_v[(size_t)BATCH*NN*TT*DD];      // 256 MB  (natural [B,N,T,D])
__device__ float g_mixed[(size_t)BATCH*NN*TT*DD];  // 256 MB  (natural [B,N,T,D])

// ---------------------------------------------------------------------------
// K1: q = z @ Wq.T, k = z @ Wk.T       (exact fp32; tiny)
// grid 2048 blocks x 256 threads; block = one (b,n) row, thread = output dim
// ---------------------------------------------------------------------------
__global__ void __launch_bounds__(256) qk_kernel(const float* __restrict__ z,
                                                 const float* __restrict__ Wq,
                                                 const float* __restrict__ Wk) {
    __shared__ float zs[DD];
    const int row = blockIdx.x;
    const int d   = threadIdx.x;
    zs[d] = z[(size_t)row*DD + d];
    __syncthreads();
    const float* wq = Wq + (size_t)d*DD;
    const float* wk = Wk + (size_t)d*DD;
    float aq = 0.f, ak = 0.f;
#pragma unroll 8
    for (int e = 0; e < DD; e++) {
        float zv = zs[e];
        aq += zv * wq[e];
        ak += zv * wk[e];
    }
    g_q[(size_t)row*DD + d] = aq;
    g_k[(size_t)row*DD + d] = ak;
}

// ---------------------------------------------------------------------------
// K2: scores, raw softmax, exact top-k threshold, masked softmax, head means.
// grid 2048 blocks (b*256+i) x 256 threads (j = key index).
// ---------------------------------------------------------------------------
__global__ void __launch_bounds__(256) attn_kernel(const float* __restrict__ adj,
                                                   float* __restrict__ out_attn_mean,
                                                   float* __restrict__ out_raw_mean) {
    const int bi = blockIdx.x;        // b*256 + i
    const int b  = bi >> 8;
    const int j  = threadIdx.x;
    const int lane = j & 31, w = j >> 5;

    __shared__ float qs[HD];
    __shared__ float sred[8];
    __shared__ int   sredi[8];

    const float scale = 0.17677669529663687f;  // 1/sqrt(32)
    const float logb = logf(fmaxf(adj[(size_t)bi*NN + j], 1e-12f));

    float mean_attn = 0.f, mean_raw = 0.f;

    for (int h = 0; h < HH; h++) {
        if (j < HD) qs[j] = g_q[(size_t)bi*DD + h*HD + j];
        __syncthreads();

        const float* kr = g_k + (size_t)(b*NN + j)*DD + h*HD;
        float s = 0.f;
#pragma unroll
        for (int e = 0; e < HD; e++) s += qs[e] * kr[e];
        s = s * scale + logb;

        // ---- block max ----
        float m = s;
#pragma unroll
        for (int o = 16; o; o >>= 1) m = fmaxf(m, __shfl_xor_sync(0xffffffffu, m, o));
        __syncthreads();           // qs reads done; sred reuse safe
        if (lane == 0) sred[w] = m;
        __syncthreads();
        m = sred[0];
#pragma unroll
        for (int x = 1; x < 8; x++) m = fmaxf(m, sred[x]);

        float p = expf(s - m);

        // ---- block sum ----
        float t = p;
#pragma unroll
        for (int o = 16; o; o >>= 1) t += __shfl_xor_sync(0xffffffffu, t, o);
        __syncthreads();
        if (lane == 0) sred[w] = t;
        __syncthreads();
        float sum = 0.f;
#pragma unroll
        for (int x = 0; x < 8; x++) sum += sred[x];
        mean_raw += p / sum;

        // ---- exact 32nd largest via 32 iterations of block argmax ----
        float cur = s;
        float kth = m;
        for (int it = 0; it < TOPK; it++) {
            float v = cur; int idx = j;
#pragma unroll
            for (int o = 16; o; o >>= 1) {
                float ov = __shfl_xor_sync(0xffffffffu, v, o);
                int   oi = __shfl_xor_sync(0xffffffffu, idx, o);
                if (ov > v || (ov == v && oi < idx)) { v = ov; idx = oi; }
            }
            __syncthreads();       // previous reads of sred complete
            if (lane == 0) { sred[w] = v; sredi[w] = idx; }
            __syncthreads();
            float bv = sred[0]; int bidx = sredi[0];
#pragma unroll
            for (int x = 1; x < 8; x++) {
                float xv = sred[x]; int xi = sredi[x];
                if (xv > bv || (xv == bv && xi < bidx)) { bv = xv; bidx = xi; }
            }
            if (j == bidx) cur = -3.402823466e38f;
            kth = bv;
        }

        // ---- masked softmax (kept entries reuse exp values; max unchanged) ----
        float pa = (s >= kth) ? p : 0.f;
        float t2 = pa;
#pragma unroll
        for (int o = 16; o; o >>= 1) t2 += __shfl_xor_sync(0xffffffffu, t2, o);
        __syncthreads();
        if (lane == 0) sred[w] = t2;
        __syncthreads();
        float sum2 = 0.f;
#pragma unroll
        for (int x = 0; x < 8; x++) sum2 += sred[x];
        float a = pa / sum2;
        mean_attn += a;

        g_attn[((size_t)(b*HH + h)*NN + (bi & 255))*NN + j] = a;
        __syncthreads();           // before next h rewrites qs
    }

    out_attn_mean[(size_t)bi*NN + j] = mean_attn * 0.125f;
    out_raw_mean[(size_t)bi*NN + j]  = mean_raw  * 0.125f;
}

// ---------------------------------------------------------------------------
// SGEMM tiles: BM=64, BN=256, BK=16, 256 threads, 8x8 microkernel.
// ---------------------------------------------------------------------------

// K3: g_v[m, n] = sum_k h_val[m,k] * Wv[n,k]      (m over B*N*T rows)
__global__ void __launch_bounds__(256) gemm_v_kernel(const float* __restrict__ A,
                                                     const float* __restrict__ W) {
    __shared__ float As[16][68];
    __shared__ float Bs[16][260];
    const int tid = threadIdx.x;
    const int tx = tid & 31, ty = tid >> 5;
    const size_t m0 = (size_t)blockIdx.x * 64;
    const int ar = tid >> 2;
    const int ak = (tid & 3) << 2;

    float acc[8][8];
#pragma unroll
    for (int r = 0; r < 8; r++)
#pragma unroll
        for (int c = 0; c < 8; c++) acc[r][c] = 0.f;

    for (int k0 = 0; k0 < DD; k0 += 16) {
        float4 av = *(const float4*)(A + (m0 + ar)*DD + k0 + ak);
        As[ak+0][ar] = av.x; As[ak+1][ar] = av.y;
        As[ak+2][ar] = av.z; As[ak+3][ar] = av.w;
#pragma unroll
        for (int u = 0; u < 4; u++) {
            int f = tid + u*256;
            int n = f >> 2;
            int kk = (f & 3) << 2;
            float4 bv = *(const float4*)(W + (size_t)n*DD + k0 + kk);
            Bs[kk+0][n] = bv.x; Bs[kk+1][n] = bv.y;
            Bs[kk+2][n] = bv.z; Bs[kk+3][n] = bv.w;
        }
        __syncthreads();
#pragma unroll
        for (int kk = 0; kk < 16; kk++) {
            float a[8], bb[8];
            *(float4*)&a[0]  = *(const float4*)&As[kk][ty*8];
            *(float4*)&a[4]  = *(const float4*)&As[kk][ty*8 + 4];
            *(float4*)&bb[0] = *(const float4*)&Bs[kk][tx*8];
            *(float4*)&bb[4] = *(const float4*)&Bs[kk][tx*8 + 4];
#pragma unroll
            for (int r = 0; r < 8; r++)
#pragma unroll
                for (int c = 0; c < 8; c++) acc[r][c] += a[r]*bb[c];
        }
        __syncthreads();
    }
#pragma unroll
    for (int r = 0; r < 8; r++) {
        size_t row = m0 + ty*8 + r;
#pragma unroll
        for (int c = 0; c < 8; c += 4) {
            float4 o = make_float4(acc[r][c], acc[r][c+1], acc[r][c+2], acc[r][c+3]);
            *(float4*)(g_v + row*DD + tx*8 + c) = o;
        }
    }
}

// K4: per (b,h): mixed[i, (t,d)] = sum_j attn[b,h,i,j] * v[b,j,t,h*32+d]
// grid: x=16 (t-blocks of 8 -> 256 cols), y=4 (i tiles of 64), z=64 (b*8+h)
__global__ void __launch_bounds__(256) gemm_mix_kernel() {
    __shared__ float As[16][68];
    __shared__ float Bs[16][260];
    const int tid = threadIdx.x;
    const int tx = tid & 31, ty = tid >> 5;
    const int bh = blockIdx.z;
    const int b = bh >> 3, h = bh & 7;
    const int i0 = blockIdx.y * 64;
    const int t0 = blockIdx.x * 8;
    const float* Aattn = g_attn + (size_t)bh * (NN*NN);
    const float* Vb    = g_v + (size_t)b * NN * TT * DD + h*HD;
    const int ar = tid >> 2;
    const int ak = (tid & 3) << 2;

    float acc[8][8];
#pragma unroll
    for (int r = 0; r < 8; r++)
#pragma unroll
        for (int c = 0; c < 8; c++) acc[r][c] = 0.f;

    for (int k0 = 0; k0 < NN; k0 += 16) {   // k = j
        float4 av = *(const float4*)(Aattn + (size_t)(i0 + ar)*NN + k0 + ak);
        As[ak+0][ar] = av.x; As[ak+1][ar] = av.y;
        As[ak+2][ar] = av.z; As[ak+3][ar] = av.w;
#pragma unroll
        for (int u = 0; u < 4; u++) {
            int f = tid + u*256;
            int jj = f >> 6;            // 0..15
            int cc = (f & 63) << 2;     // 0..252
            float4 bv = *(const float4*)(Vb + (size_t)(k0 + jj)*(TT*DD)
                                            + (t0 + (cc >> 5))*DD + (cc & 31));
            *(float4*)&Bs[jj][cc] = bv;
        }
        __syncthreads();
#pragma unroll
        for (int kk = 0; kk < 16; kk++) {
            float a[8], bb[8];
            *(float4*)&a[0]  = *(const float4*)&As[kk][ty*8];
            *(float4*)&a[4]  = *(const float4*)&As[kk][ty*8 + 4];
            *(float4*)&bb[0] = *(const float4*)&Bs[kk][tx*8];
            *(float4*)&bb[4] = *(const float4*)&Bs[kk][tx*8 + 4];
#pragma unroll
            for (int r = 0; r < 8; r++)
#pragma unroll
                for (int c = 0; c < 8; c++) acc[r][c] += a[r]*bb[c];
        }
        __syncthreads();
    }
    // store to g_mixed natural layout [b, i, t, h*32+d]
#pragma unroll
    for (int r = 0; r < 8; r++) {
        size_t base = (size_t)(b*NN + i0 + ty*8 + r)*(TT*DD);
#pragma unroll
        for (int c = 0; c < 8; c += 4) {
            int cc = tx*8 + c;
            float4 o = make_float4(acc[r][c], acc[r][c+1], acc[r][c+2], acc[r][c+3]);
            *(float4*)(g_mixed + base + (t0 + (cc >> 5))*DD + h*HD + (cc & 31)) = o;
        }
    }
}

// K5: out[m, n] = h_val[m,n] + sum_k g_mixed[m,k] * Wo[n,k]
__global__ void __launch_bounds__(256) gemm_out_kernel(const float* __restrict__ hval,
                                                       const float* __restrict__ W,
                                                       float* __restrict__ out) {
    __shared__ float As[16][68];
    __shared__ float Bs[16][260];
    const int tid = threadIdx.x;
    const int tx = tid & 31, ty = tid >> 5;
    const size_t m0 = (size_t)blockIdx.x * 64;
    const int ar = tid >> 2;
    const int ak = (tid & 3) << 2;

    float acc[8][8];
#pragma unroll
    for (int r = 0; r < 8; r++)
#pragma unroll
        for (int c = 0; c < 8; c++) acc[r][c] = 0.f;

    for (int k0 = 0; k0 < DD; k0 += 16) {
        float4 av = *(const float4*)(g_mixed + (m0 + ar)*DD + k0 + ak);
        As[ak+0][ar] = av.x; As[ak+1][ar] = av.y;
        As[ak+2][ar] = av.z; As[ak+3][ar] = av.w;
#pragma unroll
        for (int u = 0; u < 4; u++) {
            int f = tid + u*256;
            int n = f >> 2;
            int kk = (f & 3) << 2;
            float4 bv = *(const float4*)(W + (size_t)n*DD + k0 + kk);
            Bs[kk+0][n] = bv.x; Bs[kk+1][n] = bv.y;
            Bs[kk+2][n] = bv.z; Bs[kk+3][n] = bv.w;
        }
        __syncthreads();
#pragma unroll
        for (int kk = 0; kk < 16; kk++) {
            float a[8], bb[8];
            *(float4*)&a[0]  = *(const float4*)&As[kk][ty*8];
            *(float4*)&a[4]  = *(const float4*)&As[kk][ty*8 + 4];
            *(float4*)&bb[0] = *(const float4*)&Bs[kk][tx*8];
            *(float4*)&bb[4] = *(const float4*)&Bs[kk][tx*8 + 4];
#pragma unroll
            for (int r = 0; r < 8; r++)
#pragma unroll
                for (int c = 0; c < 8; c++) acc[r][c] += a[r]*bb[c];
        }
        __syncthreads();
    }
#pragma unroll
    for (int r = 0; r < 8; r++) {
        size_t row = m0 + ty*8 + r;
#pragma unroll
        for (int c = 0; c < 8; c += 4) {
            float4 hv = *(const float4*)(hval + row*DD + tx*8 + c);
            float4 o = make_float4(acc[r][c]   + hv.x, acc[r][c+1] + hv.y,
                                   acc[r][c+2] + hv.z, acc[r][c+3] + hv.w);
            *(float4*)(out + row*DD + tx*8 + c) = o;
        }
    }
}

// ---------------------------------------------------------------------------
extern "C" void kernel_launch(void* const* d_in, const int* in_sizes, int n_in,
                              void* d_out, int out_size) {
    const float* h_val = (const float*)d_in[0];
    const float* z_map = (const float*)d_in[1];
    const float* adj   = (const float*)d_in[2];
    const float* Wq    = (const float*)d_in[3];
    const float* Wk    = (const float*)d_in[4];
    const float* Wv    = (const float*)d_in[5];
    const float* Wo    = (const float*)d_in[6];

    float* out       = (float*)d_out;                     // [B,N,T,D]
    float* attn_mean = out + (size_t)BATCH*NN*TT*DD;      // [B,N,N]
    float* raw_mean  = attn_mean + (size_t)BATCH*NN*NN;   // [B,N,N]

    qk_kernel<<<BN, 256>>>(z_map, Wq, Wk);
    attn_kernel<<<BN, 256>>>(adj, attn_mean, raw_mean);
    gemm_v_kernel<<<(int)(M_BIG/64), 256>>>(h_val, Wv);
    dim3 gmix(16, 4, BATCH*HH);
    gemm_mix_kernel<<<gmix, 256>>>();
    gemm_out_kernel<<<(int)(M_BIG/64), 256>>>(h_val, Wo, out);
}

// round 2
// speedup vs baseline: 1.8121x; 1.8121x over previous
#include <cuda_runtime.h>
#include <math.h>

// Problem constants: B=8, N=256, T=128, D=256, H=8, hd=32, TOPK=32
#define BATCH 8
#define NN    256
#define TT    128
#define DD    256
#define HH    8
#define HD    32
#define TOPK  32

#define BN    (BATCH*NN)            // 2048
#define M_BIG ((size_t)BATCH*NN*TT) // 262144

// Scratch
__device__ float g_q[BN*DD];
__device__ float g_k[BN*DD];
__device__ float g_wt[4*DD*DD];                    // transposed Wq,Wk,Wv,Wo
__device__ float g_attn[(size_t)BATCH*HH*NN*NN];   // 16 MB
__device__ float g_v[(size_t)BATCH*NN*TT*DD];      // 256 MB
__device__ float g_mixed[(size_t)BATCH*NN*TT*DD];  // 256 MB

// ---------------------------------------------------------------------------
// cp.async helpers
// ---------------------------------------------------------------------------
__device__ __forceinline__ void cp16(void* dst, const void* src) {
    unsigned d = (unsigned)__cvta_generic_to_shared(dst);
    asm volatile("cp.async.cg.shared.global [%0], [%1], 16;\n" :: "r"(d), "l"(src));
}
__device__ __forceinline__ void cp_commit() { asm volatile("cp.async.commit_group;\n"); }
__device__ __forceinline__ void cp_wait1()  { asm volatile("cp.async.wait_group 1;\n"); }
__device__ __forceinline__ void cp_wait0()  { asm volatile("cp.async.wait_group 0;\n"); }

// ---------------------------------------------------------------------------
// K0: transpose all 4 weight matrices:  g_wt[w][k][n] = W_w[n][k]
// grid (8,8,4), block (32,8)
// ---------------------------------------------------------------------------
__global__ void transpose_w_kernel(const float* __restrict__ Wq, const float* __restrict__ Wk,
                                   const float* __restrict__ Wv, const float* __restrict__ Wo) {
    __shared__ float t[32][33];
    const int w = blockIdx.z;
    const float* W = (w == 0) ? Wq : (w == 1) ? Wk : (w == 2) ? Wv : Wo;
    float* out = g_wt + (size_t)w * DD * DD;
    const int n0 = blockIdx.x * 32, k0 = blockIdx.y * 32;
    const int tx = threadIdx.x, ty = threadIdx.y;
#pragma unroll
    for (int i = 0; i < 4; i++)
        t[ty + 8*i][tx] = W[(size_t)(n0 + ty + 8*i)*DD + k0 + tx];
    __syncthreads();
#pragma unroll
    for (int i = 0; i < 4; i++)
        out[(size_t)(k0 + ty + 8*i)*DD + n0 + tx] = t[tx][ty + 8*i];
}

// ---------------------------------------------------------------------------
// Shared GEMM body macro pieces (BM=64, BN=256, BK=16, 256 thr, 8x8 micro)
// A is [M,256] row-major; B comes from k-major WT rows (cp.async-able).
// ---------------------------------------------------------------------------
#define GEMM_DECL \
    __shared__ float As[2][16][68];  \
    __shared__ float Bs[2][16][260]; \
    const int tid = threadIdx.x;     \
    const int tx = tid & 31, ty = tid >> 5; \
    const int ar = tid >> 2;         \
    const int ak = (tid & 3) << 2;   \
    float acc[8][8];                 \
    _Pragma("unroll") for (int r = 0; r < 8; r++) \
    _Pragma("unroll") for (int c = 0; c < 8; c++) acc[r][c] = 0.f;

#define GEMM_COMPUTE(buf) \
    _Pragma("unroll") \
    for (int kk = 0; kk < 16; kk++) { \
        float a[8], bb[8]; \
        *(float4*)&a[0]  = *(const float4*)&As[buf][kk][ty*8]; \
        *(float4*)&a[4]  = *(const float4*)&As[buf][kk][ty*8 + 4]; \
        *(float4*)&bb[0] = *(const float4*)&Bs[buf][kk][tx*8]; \
        *(float4*)&bb[4] = *(const float4*)&Bs[buf][kk][tx*8 + 4]; \
        _Pragma("unroll") for (int r = 0; r < 8; r++) \
        _Pragma("unroll") for (int c = 0; c < 8; c++) acc[r][c] += a[r]*bb[c]; \
    }

// ---------------------------------------------------------------------------
// K1: q/k projection GEMM.  grid (32, 2): y=0 -> q (WT=WqT), y=1 -> k (WkT)
// ---------------------------------------------------------------------------
__global__ void __launch_bounds__(256) gemm_qk_kernel(const float* __restrict__ Z) {
    GEMM_DECL
    const int wsel = blockIdx.y;
    const float* WT = g_wt + (size_t)wsel * DD * DD;
    float* out = wsel ? g_k : g_q;
    const size_t m0 = (size_t)blockIdx.x * 64;

#pragma unroll
    for (int u = 0; u < 4; u++) {
        int f = tid + u*256; int jj = f >> 6; int cc = (f & 63) << 2;
        cp16(&Bs[0][jj][cc], WT + (size_t)jj*DD + cc);
    }
    cp_commit();
    float4 av = *(const float4*)(Z + (m0 + ar)*DD + ak);
    As[0][ak+0][ar] = av.x; As[0][ak+1][ar] = av.y;
    As[0][ak+2][ar] = av.z; As[0][ak+3][ar] = av.w;

    for (int k = 0; k < 16; k++) {
        const int cur = k & 1;
        if (k < 15) {
            av = *(const float4*)(Z + (m0 + ar)*DD + (k+1)*16 + ak);
#pragma unroll
            for (int u = 0; u < 4; u++) {
                int f = tid + u*256; int jj = f >> 6; int cc = (f & 63) << 2;
                cp16(&Bs[cur^1][jj][cc], WT + (size_t)((k+1)*16 + jj)*DD + cc);
            }
            cp_commit(); cp_wait1();
        } else cp_wait0();
        __syncthreads();
        GEMM_COMPUTE(cur)
        __syncthreads();
        if (k < 15) {
            As[cur^1][ak+0][ar] = av.x; As[cur^1][ak+1][ar] = av.y;
            As[cur^1][ak+2][ar] = av.z; As[cur^1][ak+3][ar] = av.w;
        }
    }
#pragma unroll
    for (int r = 0; r < 8; r++) {
        size_t row = m0 + ty*8 + r;
#pragma unroll
        for (int c = 0; c < 8; c += 4) {
            float4 o = make_float4(acc[r][c], acc[r][c+1], acc[r][c+2], acc[r][c+3]);
            *(float4*)(out + row*DD + tx*8 + c) = o;
        }
    }
}

// ---------------------------------------------------------------------------
// K2: attention — warp h handles head h of row (b,i). No block syncs in hot path.
// grid 2048, block 256, dynamic smem.
// ---------------------------------------------------------------------------
#define SWAP_DESC(a, b) { float _hi = fmaxf(a, b); b = fminf(a, b); a = _hi; }

__global__ void __launch_bounds__(256) attn_kernel(const float* __restrict__ adj,
                                                   float* __restrict__ out_attn_mean,
                                                   float* __restrict__ out_raw_mean) {
    extern __shared__ float sm[];
    float* kss   = sm;                 // 64*257
    float* logbs = kss + 64*257;       // 256
    float* qsh   = logbs + 256;        // 256
    float* asum  = qsh + 256;          // 8*256
    float* rsum  = asum + 8*256;       // 8*256

    const int bi = blockIdx.x, b = bi >> 8, i = bi & 255;
    const int tid = threadIdx.x, lane = tid & 31, h = tid >> 5;
    const float scale = 0.17677669529663687f;

    logbs[tid] = logf(fmaxf(adj[(size_t)bi*NN + tid], 1e-12f));
    qsh[tid]   = g_q[(size_t)bi*DD + tid];
    __syncthreads();

    float qreg[32];
#pragma unroll
    for (int e = 0; e < 32; e++) qreg[e] = qsh[h*HD + e];

    float sreg[8];
    for (int jt = 0; jt < 4; jt++) {
        if (jt) __syncthreads();
        const float* ksrc = g_k + ((size_t)(b*NN) + jt*64) * DD;
#pragma unroll
        for (int u = 0; u < 16; u++) {
            int f = tid + u*256;
            int r = f >> 6, c = (f & 63) << 2;
            float4 kv = *(const float4*)(ksrc + (size_t)f*4);
            kss[r*257 + c + 0] = kv.x; kss[r*257 + c + 1] = kv.y;
            kss[r*257 + c + 2] = kv.z; kss[r*257 + c + 3] = kv.w;
        }
        __syncthreads();
#pragma unroll
        for (int g = 0; g < 2; g++) {
            int jl = g*32 + lane;
            const float* kp = &kss[jl*257 + h*HD];
            float s = 0.f;
#pragma unroll
            for (int e = 0; e < 32; e++) s += qreg[e] * kp[e];
            sreg[jt*2 + g] = s * scale + logbs[jt*64 + jl];
        }
    }

    // raw softmax
    float m = sreg[0];
#pragma unroll
    for (int x = 1; x < 8; x++) m = fmaxf(m, sreg[x]);
#pragma unroll
    for (int o = 16; o; o >>= 1) m = fmaxf(m, __shfl_xor_sync(0xffffffffu, m, o));
    float preg[8], tsum = 0.f;
#pragma unroll
    for (int x = 0; x < 8; x++) { preg[x] = expf(sreg[x] - m); tsum += preg[x]; }
#pragma unroll
    for (int o = 16; o; o >>= 1) tsum += __shfl_xor_sync(0xffffffffu, tsum, o);

    // exact 32nd largest: per-lane Batcher sort-8 (desc) + 32 warp-max pops
    float v0 = sreg[0], v1 = sreg[1], v2 = sreg[2], v3 = sreg[3];
    float v4 = sreg[4], v5 = sreg[5], v6 = sreg[6], v7 = sreg[7];
    SWAP_DESC(v0,v1) SWAP_DESC(v2,v3) SWAP_DESC(v4,v5) SWAP_DESC(v6,v7)
    SWAP_DESC(v0,v2) SWAP_DESC(v1,v3) SWAP_DESC(v4,v6) SWAP_DESC(v5,v7)
    SWAP_DESC(v1,v2) SWAP_DESC(v5,v6)
    SWAP_DESC(v0,v4) SWAP_DESC(v1,v5) SWAP_DESC(v2,v6) SWAP_DESC(v3,v7)
    SWAP_DESC(v2,v4) SWAP_DESC(v3,v5)
    SWAP_DESC(v1,v2) SWAP_DESC(v3,v4) SWAP_DESC(v5,v6)

    float kth = 0.f;
#pragma unroll 1
    for (int it = 0; it < TOPK; it++) {
        float mm = v0;
#pragma unroll
        for (int o = 16; o; o >>= 1) mm = fmaxf(mm, __shfl_xor_sync(0xffffffffu, mm, o));
        if (it == TOPK-1) { kth = mm; break; }
        unsigned bal = __ballot_sync(0xffffffffu, v0 == mm);
        if (lane == (__ffs(bal) - 1)) {
            v0 = v1; v1 = v2; v2 = v3; v3 = v4; v4 = v5; v5 = v6; v6 = v7;
            v7 = -3.402823466e38f;
        }
    }

    // masked softmax (reuse exp values; row max always kept)
    float pa[8], ts2 = 0.f;
#pragma unroll
    for (int x = 0; x < 8; x++) { pa[x] = (sreg[x] >= kth) ? preg[x] : 0.f; ts2 += pa[x]; }
#pragma unroll
    for (int o = 16; o; o >>= 1) ts2 += __shfl_xor_sync(0xffffffffu, ts2, o);

    const float inv2 = 1.f / ts2, inv1 = 1.f / tsum;
    float* arow = g_attn + ((size_t)(b*HH + h)*NN + i)*NN;
#pragma unroll
    for (int x = 0; x < 8; x++) {
        int j = (x >> 1)*64 + (x & 1)*32 + lane;
        float a = pa[x] * inv2;
        arow[j] = a;
        asum[h*256 + j] = a;
        rsum[h*256 + j] = preg[x] * inv1;
    }
    __syncthreads();
    float sa = 0.f, sr = 0.f;
#pragma unroll
    for (int hh = 0; hh < 8; hh++) { sa += asum[hh*256 + tid]; sr += rsum[hh*256 + tid]; }
    out_attn_mean[(size_t)bi*NN + tid] = sa * 0.125f;
    out_raw_mean[(size_t)bi*NN + tid]  = sr * 0.125f;
}

// ---------------------------------------------------------------------------
// K3: g_v[m,n] = sum_k h_val[m,k] * WvT[k,n]
// ---------------------------------------------------------------------------
__global__ void __launch_bounds__(256) gemm_v_kernel(const float* __restrict__ A) {
    GEMM_DECL
    const float* WT = g_wt + (size_t)2 * DD * DD;
    const size_t m0 = (size_t)blockIdx.x * 64;

#pragma unroll
    for (int u = 0; u < 4; u++) {
        int f = tid + u*256; int jj = f >> 6; int cc = (f & 63) << 2;
        cp16(&Bs[0][jj][cc], WT + (size_t)jj*DD + cc);
    }
    cp_commit();
    float4 av = *(const float4*)(A + (m0 + ar)*DD + ak);
    As[0][ak+0][ar] = av.x; As[0][ak+1][ar] = av.y;
    As[0][ak+2][ar] = av.z; As[0][ak+3][ar] = av.w;

    for (int k = 0; k < 16; k++) {
        const int cur = k & 1;
        if (k < 15) {
            av = *(const float4*)(A + (m0 + ar)*DD + (k+1)*16 + ak);
#pragma unroll
            for (int u = 0; u < 4; u++) {
                int f = tid + u*256; int jj = f >> 6; int cc = (f & 63) << 2;
                cp16(&Bs[cur^1][jj][cc], WT + (size_t)((k+1)*16 + jj)*DD + cc);
            }
            cp_commit(); cp_wait1();
        } else cp_wait0();
        __syncthreads();
        GEMM_COMPUTE(cur)
        __syncthreads();
        if (k < 15) {
            As[cur^1][ak+0][ar] = av.x; As[cur^1][ak+1][ar] = av.y;
            As[cur^1][ak+2][ar] = av.z; As[cur^1][ak+3][ar] = av.w;
        }
    }
#pragma unroll
    for (int r = 0; r < 8; r++) {
        size_t row = m0 + ty*8 + r;
#pragma unroll
        for (int c = 0; c < 8; c += 4) {
            float4 o = make_float4(acc[r][c], acc[r][c+1], acc[r][c+2], acc[r][c+3]);
            *(float4*)(g_v + row*DD + tx*8 + c) = o;
        }
    }
}

// ---------------------------------------------------------------------------
// K4: mix — per (b,h): mixed[i,(t,d)] = sum_j attn[b,h,i,j]*v[b,j,t,h*32+d]
// grid (16, 4, 64)
// ---------------------------------------------------------------------------
__global__ void __launch_bounds__(256) gemm_mix_kernel() {
    GEMM_DECL
    const int bh = blockIdx.z;
    const int b = bh >> 3, h = bh & 7;
    const int i0 = blockIdx.y * 64;
    const int t0 = blockIdx.x * 8;
    const float* Aattn = g_attn + (size_t)bh * (NN*NN);
    const float* Vb    = g_v + (size_t)b * NN * TT * DD + h*HD;

#pragma unroll
    for (int u = 0; u < 4; u++) {
        int f = tid + u*256; int jj = f >> 6; int cc = (f & 63) << 2;
        cp16(&Bs[0][jj][cc], Vb + (size_t)jj*(TT*DD) + (t0 + (cc >> 5))*DD + (cc & 31));
    }
    cp_commit();
    float4 av = *(const float4*)(Aattn + (size_t)(i0 + ar)*NN + ak);
    As[0][ak+0][ar] = av.x; As[0][ak+1][ar] = av.y;
    As[0][ak+2][ar] = av.z; As[0][ak+3][ar] = av.w;

    for (int k = 0; k < 16; k++) {
        const int cur = k & 1;
        if (k < 15) {
            av = *(const float4*)(Aattn + (size_t)(i0 + ar)*NN + (k+1)*16 + ak);
#pragma unroll
            for (int u = 0; u < 4; u++) {
                int f = tid + u*256; int jj = f >> 6; int cc = (f & 63) << 2;
                cp16(&Bs[cur^1][jj][cc],
                     Vb + (size_t)((k+1)*16 + jj)*(TT*DD) + (t0 + (cc >> 5))*DD + (cc & 31));
            }
            cp_commit(); cp_wait1();
        } else cp_wait0();
        __syncthreads();
        GEMM_COMPUTE(cur)
        __syncthreads();
        if (k < 15) {
            As[cur^1][ak+0][ar] = av.x; As[cur^1][ak+1][ar] = av.y;
            As[cur^1][ak+2][ar] = av.z; As[cur^1][ak+3][ar] = av.w;
        }
    }
#pragma unroll
    for (int r = 0; r < 8; r++) {
        size_t base = (size_t)(b*NN + i0 + ty*8 + r)*(TT*DD);
#pragma unroll
        for (int c = 0; c < 8; c += 4) {
            int cc = tx*8 + c;
            float4 o = make_float4(acc[r][c], acc[r][c+1], acc[r][c+2], acc[r][c+3]);
            *(float4*)(g_mixed + base + (t0 + (cc >> 5))*DD + h*HD + (cc & 31)) = o;
        }
    }
}

// ---------------------------------------------------------------------------
// K5: out[m,n] = h_val[m,n] + sum_k g_mixed[m,k] * WoT[k,n]
// ---------------------------------------------------------------------------
__global__ void __launch_bounds__(256) gemm_out_kernel(const float* __restrict__ hval,
                                                       float* __restrict__ out) {
    GEMM_DECL
    const float* WT = g_wt + (size_t)3 * DD * DD;
    const size_t m0 = (size_t)blockIdx.x * 64;

#pragma unroll
    for (int u = 0; u < 4; u++) {
        int f = tid + u*256; int jj = f >> 6; int cc = (f & 63) << 2;
        cp16(&Bs[0][jj][cc], WT + (size_t)jj*DD + cc);
    }
    cp_commit();
    float4 av = *(const float4*)(g_mixed + (m0 + ar)*DD + ak);
    As[0][ak+0][ar] = av.x; As[0][ak+1][ar] = av.y;
    As[0][ak+2][ar] = av.z; As[0][ak+3][ar] = av.w;

    for (int k = 0; k < 16; k++) {
        const int cur = k & 1;
        if (k < 15) {
            av = *(const float4*)(g_mixed + (m0 + ar)*DD + (k+1)*16 + ak);
#pragma unroll
            for (int u = 0; u < 4; u++) {
                int f = tid + u*256; int jj = f >> 6; int cc = (f & 63) << 2;
                cp16(&Bs[cur^1][jj][cc], WT + (size_t)((k+1)*16 + jj)*DD + cc);
            }
            cp_commit(); cp_wait1();
        } else cp_wait0();
        __syncthreads();
        GEMM_COMPUTE(cur)
        __syncthreads();
        if (k < 15) {
            As[cur^1][ak+0][ar] = av.x; As[cur^1][ak+1][ar] = av.y;
            As[cur^1][ak+2][ar] = av.z; As[cur^1][ak+3][ar] = av.w;
        }
    }
#pragma unroll
    for (int r = 0; r < 8; r++) {
        size_t row = m0 + ty*8 + r;
#pragma unroll
        for (int c = 0; c < 8; c += 4) {
            float4 hv = *(const float4*)(hval + row*DD + tx*8 + c);
            float4 o = make_float4(acc[r][c]   + hv.x, acc[r][c+1] + hv.y,
                                   acc[r][c+2] + hv.z, acc[r][c+3] + hv.w);
            *(float4*)(out + row*DD + tx*8 + c) = o;
        }
    }
}

// ---------------------------------------------------------------------------
extern "C" void kernel_launch(void* const* d_in, const int* in_sizes, int n_in,
                              void* d_out, int out_size) {
    const float* h_val = (const float*)d_in[0];
    const float* z_map = (const float*)d_in[1];
    const float* adj   = (const float*)d_in[2];
    const float* Wq    = (const float*)d_in[3];
    const float* Wk    = (const float*)d_in[4];
    const float* Wv    = (const float*)d_in[5];
    const float* Wo    = (const float*)d_in[6];

    float* out       = (float*)d_out;
    float* attn_mean = out + (size_t)BATCH*NN*TT*DD;
    float* raw_mean  = attn_mean + (size_t)BATCH*NN*NN;

    // attn dynamic smem: kss + logbs + qsh + asum + rsum
    const int attn_smem = (64*257 + 256 + 256 + 8*256 + 8*256) * (int)sizeof(float);
    static bool configured = false;
    if (!configured) {
        cudaFuncSetAttribute(attn_kernel, cudaFuncAttributeMaxDynamicSharedMemorySize, attn_smem);
        configured = true;
    }

    dim3 tgrid(8, 8, 4), tblk(32, 8);
    transpose_w_kernel<<<tgrid, tblk>>>(Wq, Wk, Wv, Wo);
    dim3 qkgrid(32, 2);
    gemm_qk_kernel<<<qkgrid, 256>>>(z_map);
    attn_kernel<<<BN, 256, attn_smem>>>(adj, attn_mean, raw_mean);
    gemm_v_kernel<<<(int)(M_BIG/64), 256>>>(h_val);
    dim3 gmix(16, 4, BATCH*HH);
    gemm_mix_kernel<<<gmix, 256>>>();
    gemm_out_kernel<<<(int)(M_BIG/64), 256>>>(h_val, out);
}

// round 8
// speedup vs baseline: 2.5718x; 1.4192x over previous
#include <cuda_runtime.h>
#include <cuda_bf16.h>
#include <mma.h>
#include <math.h>
#include <stdint.h>

using namespace nvcuda;

// Problem constants: B=8, N=256, T=128, D=256, H=8, hd=32, TOPK=32
#define BATCH 8
#define NN    256
#define TT    128
#define DD    256
#define HH    8
#define HD    32
#define TOPK  32

#define BN    (BATCH*NN)            // 2048
#define M_BIG ((size_t)BATCH*NN*TT) // 262144

// Scratch (accessed ONLY from device code — never passed as kernel args)
__device__ float g_q[BN*DD];
__device__ float g_k[BN*DD];
__device__ float g_wt[2*DD*DD];                    // transposed Wq,Wk
__device__ float g_attn[(size_t)BATCH*HH*NN*NN];   // 16 MB
__device__ float g_v[(size_t)BATCH*NN*TT*DD];      // 256 MB
__device__ float g_mixed[(size_t)BATCH*NN*TT*DD];  // 256 MB

typedef wmma::fragment<wmma::matrix_a, 16, 16, 16, __nv_bfloat16, wmma::row_major> FragA;
typedef wmma::fragment<wmma::matrix_b, 16, 16, 16, __nv_bfloat16, wmma::col_major> FragBc;
typedef wmma::fragment<wmma::matrix_b, 16, 16, 16, __nv_bfloat16, wmma::row_major> FragBr;
typedef wmma::fragment<wmma::accumulator, 16, 16, 16, float> FragC;

// ---------------------------------------------------------------------------
// helpers
// ---------------------------------------------------------------------------
__device__ __forceinline__ void cp16(void* dst, const void* src) {
    unsigned d = (unsigned)__cvta_generic_to_shared(dst);
    asm volatile("cp.async.cg.shared.global [%0], [%1], 16;\n" :: "r"(d), "l"(src));
}
__device__ __forceinline__ void cp_commit() { asm volatile("cp.async.commit_group;\n"); }
__device__ __forceinline__ void cp_wait1()  { asm volatile("cp.async.wait_group 1;\n"); }
__device__ __forceinline__ void cp_wait0()  { asm volatile("cp.async.wait_group 0;\n"); }

// fp32 -> (bf16 hi, bf16 lo) split, plain element stores (no punning).
__device__ __forceinline__ void bf_split_store4(__nv_bfloat16* hp, __nv_bfloat16* lp,
                                                float4 v) {
    float vv0 = v.x, vv1 = v.y, vv2 = v.z, vv3 = v.w;
    __nv_bfloat16 h0 = __float2bfloat16_rn(vv0);
    __nv_bfloat16 h1 = __float2bfloat16_rn(vv1);
    __nv_bfloat16 h2 = __float2bfloat16_rn(vv2);
    __nv_bfloat16 h3 = __float2bfloat16_rn(vv3);
    hp[0] = h0; hp[1] = h1; hp[2] = h2; hp[3] = h3;
    lp[0] = __float2bfloat16_rn(vv0 - __bfloat162float(h0));
    lp[1] = __float2bfloat16_rn(vv1 - __bfloat162float(h1));
    lp[2] = __float2bfloat16_rn(vv2 - __bfloat162float(h2));
    lp[3] = __float2bfloat16_rn(vv3 - __bfloat162float(h3));
}

// ---------------------------------------------------------------------------
// K0: transpose Wq, Wk  -> g_wt.  grid (8,8,2), block (32,8)
// ---------------------------------------------------------------------------
__global__ void transpose_w_kernel(const float* __restrict__ Wq, const float* __restrict__ Wk) {
    __shared__ float t[32][33];
    const int w = blockIdx.z;
    const float* W = (w == 0) ? Wq : Wk;
    float* out = g_wt + (size_t)w * DD * DD;
    const int n0 = blockIdx.x * 32, k0 = blockIdx.y * 32;
    const int tx = threadIdx.x, ty = threadIdx.y;
#pragma unroll
    for (int i = 0; i < 4; i++)
        t[ty + 8*i][tx] = W[(size_t)(n0 + ty + 8*i)*DD + k0 + tx];
    __syncthreads();
#pragma unroll
    for (int i = 0; i < 4; i++)
        out[(size_t)(k0 + ty + 8*i)*DD + n0 + tx] = t[tx][ty + 8*i];
}

// ---------------------------------------------------------------------------
// SIMT GEMM macros (qk only)
// ---------------------------------------------------------------------------
#define GEMM_DECL \
    __shared__ float As[2][16][68];  \
    __shared__ float Bs[2][16][260]; \
    const int tid = threadIdx.x;     \
    const int tx = tid & 31, ty = tid >> 5; \
    const int ar = tid >> 2;         \
    const int ak = (tid & 3) << 2;   \
    float acc[8][8];                 \
    _Pragma("unroll") for (int r = 0; r < 8; r++) \
    _Pragma("unroll") for (int c = 0; c < 8; c++) acc[r][c] = 0.f;

#define GEMM_COMPUTE(buf) \
    _Pragma("unroll") \
    for (int kk = 0; kk < 16; kk++) { \
        float a[8], bb[8]; \
        *(float4*)&a[0]  = *(const float4*)&As[buf][kk][ty*8]; \
        *(float4*)&a[4]  = *(const float4*)&As[buf][kk][ty*8 + 4]; \
        *(float4*)&bb[0] = *(const float4*)&Bs[buf][kk][tx*8]; \
        *(float4*)&bb[4] = *(const float4*)&Bs[buf][kk][tx*8 + 4]; \
        _Pragma("unroll") for (int r = 0; r < 8; r++) \
        _Pragma("unroll") for (int c = 0; c < 8; c++) acc[r][c] += a[r]*bb[c]; \
    }

// ---------------------------------------------------------------------------
// K1: q/k projection GEMM.  grid (32, 2): y=0 -> q, y=1 -> k
// ---------------------------------------------------------------------------
__global__ void __launch_bounds__(256) gemm_qk_kernel(const float* __restrict__ Z) {
    GEMM_DECL
    const int wsel = blockIdx.y;
    const float* WT = g_wt + (size_t)wsel * DD * DD;
    float* out = wsel ? g_k : g_q;
    const size_t m0 = (size_t)blockIdx.x * 64;

#pragma unroll
    for (int u = 0; u < 4; u++) {
        int f = tid + u*256; int jj = f >> 6; int cc = (f & 63) << 2;
        cp16(&Bs[0][jj][cc], WT + (size_t)jj*DD + cc);
    }
    cp_commit();
    float4 av = *(const float4*)(Z + (m0 + ar)*DD + ak);
    As[0][ak+0][ar] = av.x; As[0][ak+1][ar] = av.y;
    As[0][ak+2][ar] = av.z; As[0][ak+3][ar] = av.w;

    for (int k = 0; k < 16; k++) {
        const int cur = k & 1;
        if (k < 15) {
            av = *(const float4*)(Z + (m0 + ar)*DD + (k+1)*16 + ak);
#pragma unroll
            for (int u = 0; u < 4; u++) {
                int f = tid + u*256; int jj = f >> 6; int cc = (f & 63) << 2;
                cp16(&Bs[cur^1][jj][cc], WT + (size_t)((k+1)*16 + jj)*DD + cc);
            }
            cp_commit(); cp_wait1();
        } else cp_wait0();
        __syncthreads();
        GEMM_COMPUTE(cur)
        __syncthreads();
        if (k < 15) {
            As[cur^1][ak+0][ar] = av.x; As[cur^1][ak+1][ar] = av.y;
            As[cur^1][ak+2][ar] = av.z; As[cur^1][ak+3][ar] = av.w;
        }
    }
#pragma unroll
    for (int r = 0; r < 8; r++) {
        size_t row = m0 + ty*8 + r;
#pragma unroll
        for (int c = 0; c < 8; c += 4) {
            float4 o = make_float4(acc[r][c], acc[r][c+1], acc[r][c+2], acc[r][c+3]);
            *(float4*)(out + row*DD + tx*8 + c) = o;
        }
    }
}

// ---------------------------------------------------------------------------
// K2: attention — warp h handles head h of row (b,i).
// ---------------------------------------------------------------------------
#define SWAP_DESC(a, b) { float _hi = fmaxf(a, b); b = fminf(a, b); a = _hi; }

__global__ void __launch_bounds__(256) attn_kernel(const float* __restrict__ adj,
                                                   float* __restrict__ out_attn_mean,
                                                   float* __restrict__ out_raw_mean) {
    extern __shared__ float sm[];
    float* kss   = sm;
    float* logbs = kss + 64*257;
    float* qsh   = logbs + 256;
    float* asum  = qsh + 256;
    float* rsum  = asum + 8*256;

    const int bi = blockIdx.x, b = bi >> 8, i = bi & 255;
    const int tid = threadIdx.x, lane = tid & 31, h = tid >> 5;
    const float scale = 0.17677669529663687f;

    logbs[tid] = logf(fmaxf(adj[(size_t)bi*NN + tid], 1e-12f));
    qsh[tid]   = g_q[(size_t)bi*DD + tid];
    __syncthreads();

    float qreg[32];
#pragma unroll
    for (int e = 0; e < 32; e++) qreg[e] = qsh[h*HD + e];

    float sreg[8];
    for (int jt = 0; jt < 4; jt++) {
        if (jt) __syncthreads();
        const float* ksrc = g_k + ((size_t)(b*NN) + jt*64) * DD;
#pragma unroll
        for (int u = 0; u < 16; u++) {
            int f = tid + u*256;
            int r = f >> 6, c = (f & 63) << 2;
            float4 kv = *(const float4*)(ksrc + (size_t)f*4);
            kss[r*257 + c + 0] = kv.x; kss[r*257 + c + 1] = kv.y;
            kss[r*257 + c + 2] = kv.z; kss[r*257 + c + 3] = kv.w;
        }
        __syncthreads();
#pragma unroll
        for (int g = 0; g < 2; g++) {
            int jl = g*32 + lane;
            const float* kp = &kss[jl*257 + h*HD];
            float s = 0.f;
#pragma unroll
            for (int e = 0; e < 32; e++) s += qreg[e] * kp[e];
            sreg[jt*2 + g] = s * scale + logbs[jt*64 + jl];
        }
    }

    float m = sreg[0];
#pragma unroll
    for (int x = 1; x < 8; x++) m = fmaxf(m, sreg[x]);
#pragma unroll
    for (int o = 16; o; o >>= 1) m = fmaxf(m, __shfl_xor_sync(0xffffffffu, m, o));
    float preg[8], tsum = 0.f;
#pragma unroll
    for (int x = 0; x < 8; x++) { preg[x] = expf(sreg[x] - m); tsum += preg[x]; }
#pragma unroll
    for (int o = 16; o; o >>= 1) tsum += __shfl_xor_sync(0xffffffffu, tsum, o);

    float v0 = sreg[0], v1 = sreg[1], v2 = sreg[2], v3 = sreg[3];
    float v4 = sreg[4], v5 = sreg[5], v6 = sreg[6], v7 = sreg[7];
    SWAP_DESC(v0,v1) SWAP_DESC(v2,v3) SWAP_DESC(v4,v5) SWAP_DESC(v6,v7)
    SWAP_DESC(v0,v2) SWAP_DESC(v1,v3) SWAP_DESC(v4,v6) SWAP_DESC(v5,v7)
    SWAP_DESC(v1,v2) SWAP_DESC(v5,v6)
    SWAP_DESC(v0,v4) SWAP_DESC(v1,v5) SWAP_DESC(v2,v6) SWAP_DESC(v3,v7)
    SWAP_DESC(v2,v4) SWAP_DESC(v3,v5)
    SWAP_DESC(v1,v2) SWAP_DESC(v3,v4) SWAP_DESC(v5,v6)

    float kth = 0.f;
#pragma unroll 1
    for (int it = 0; it < TOPK; it++) {
        float mm = v0;
#pragma unroll
        for (int o = 16; o; o >>= 1) mm = fmaxf(mm, __shfl_xor_sync(0xffffffffu, mm, o));
        if (it == TOPK-1) { kth = mm; break; }
        unsigned bal = __ballot_sync(0xffffffffu, v0 == mm);
        if (lane == (__ffs(bal) - 1)) {
            v0 = v1; v1 = v2; v2 = v3; v3 = v4; v4 = v5; v5 = v6; v6 = v7;
            v7 = -3.402823466e38f;
        }
    }

    float pa[8], ts2 = 0.f;
#pragma unroll
    for (int x = 0; x < 8; x++) { pa[x] = (sreg[x] >= kth) ? preg[x] : 0.f; ts2 += pa[x]; }
#pragma unroll
    for (int o = 16; o; o >>= 1) ts2 += __shfl_xor_sync(0xffffffffu, ts2, o);

    const float inv2 = 1.f / ts2, inv1 = 1.f / tsum;
    float* arow = g_attn + ((size_t)(b*HH + h)*NN + i)*NN;
#pragma unroll
    for (int x = 0; x < 8; x++) {
        int j = (x >> 1)*64 + (x & 1)*32 + lane;
        float a = pa[x] * inv2;
        arow[j] = a;
        asum[h*256 + j] = a;
        rsum[h*256 + j] = preg[x] * inv1;
    }
    __syncthreads();
    float sa = 0.f, sr = 0.f;
#pragma unroll
    for (int hh = 0; hh < 8; hh++) { sa += asum[hh*256 + tid]; sr += rsum[hh*256 + tid]; }
    out_attn_mean[(size_t)bi*NN + tid] = sa * 0.125f;
    out_raw_mean[(size_t)bi*NN + tid]  = sr * 0.125f;
}

// ---------------------------------------------------------------------------
// K3/K5: bf16x3 WMMA GEMM vs weights.
// mode 0:  g_v[m,n]  = sum_k Aext[m,k]*W[n,k]           (Aext = h_val)
// mode 1:  outExt[m,n] = resid[m,n] + sum_k g_mixed[m,k]*W[n,k]
// Device globals are resolved INSIDE device code (never via host args).
// grid (2048, 2), 256 thr; tile 128x128x32; 8 warps of 64x32.
// ---------------------------------------------------------------------------
__global__ void __launch_bounds__(256) wgemm_kernel(const float* __restrict__ Aext,
                                                    const float* __restrict__ W,
                                                    float* __restrict__ outExt,
                                                    const float* __restrict__ residExt,
                                                    int mode) {
    const float* A      = mode ? (const float*)g_mixed : Aext;
    float*       outp   = mode ? outExt : (float*)g_v;
    const float* resid  = mode ? residExt : nullptr;

    __shared__ __align__(32) __nv_bfloat16 smem[4*5120];   // 40960 B
    __nv_bfloat16* Ah = smem;
    __nv_bfloat16* Al = smem + 5120;
    __nv_bfloat16* Bh = smem + 10240;
    __nv_bfloat16* Bl = smem + 15360;

    const int tid = threadIdx.x, wid = tid >> 5;
    const size_t m0 = (size_t)blockIdx.x * 128;
    const int n0 = blockIdx.y * 128;
    const int sr = tid >> 3, sk4 = (tid & 7) * 4;
    const int m_base = (wid & 1) * 64;
    const int n_base = (wid >> 1) * 32;

    FragC acc[4][2];
#pragma unroll
    for (int mt = 0; mt < 4; mt++)
#pragma unroll
        for (int nt = 0; nt < 2; nt++) wmma::fill_fragment(acc[mt][nt], 0.0f);

    float4 areg[4], breg[4];
    auto LOAD = [&](int c) {
#pragma unroll
        for (int u = 0; u < 4; u++) {
            areg[u] = *(const float4*)(A + (m0 + sr + u*32)*DD + c*32 + sk4);
            breg[u] = *(const float4*)(W + (size_t)(n0 + sr + u*32)*DD + c*32 + sk4);
        }
    };
    auto STORE = [&]() {
#pragma unroll
        for (int u = 0; u < 4; u++) {
            int off = (sr + u*32)*40 + sk4;
            bf_split_store4(Ah + off, Al + off, areg[u]);
            bf_split_store4(Bh + off, Bl + off, breg[u]);
        }
    };
    auto COMPUTE = [&]() {
#pragma unroll
        for (int ks = 0; ks < 2; ks++) {
            FragA  af[4];
            FragBc bhf[2], blf[2];
#pragma unroll
            for (int mt = 0; mt < 4; mt++)
                wmma::load_matrix_sync(af[mt], Ah + (m_base + mt*16)*40 + ks*16, 40);
#pragma unroll
            for (int nt = 0; nt < 2; nt++) {
                wmma::load_matrix_sync(bhf[nt], Bh + (n_base + nt*16)*40 + ks*16, 40);
                wmma::load_matrix_sync(blf[nt], Bl + (n_base + nt*16)*40 + ks*16, 40);
            }
#pragma unroll
            for (int mt = 0; mt < 4; mt++)
#pragma unroll
                for (int nt = 0; nt < 2; nt++) {
                    wmma::mma_sync(acc[mt][nt], af[mt], bhf[nt], acc[mt][nt]);
                    wmma::mma_sync(acc[mt][nt], af[mt], blf[nt], acc[mt][nt]);
                }
#pragma unroll
            for (int mt = 0; mt < 4; mt++)
                wmma::load_matrix_sync(af[mt], Al + (m_base + mt*16)*40 + ks*16, 40);
#pragma unroll
            for (int mt = 0; mt < 4; mt++)
#pragma unroll
                for (int nt = 0; nt < 2; nt++)
                    wmma::mma_sync(acc[mt][nt], af[mt], bhf[nt], acc[mt][nt]);
        }
    };

    LOAD(0);
    STORE();
    __syncthreads();
    for (int c = 0; c < 8; c++) {
        if (c < 7) LOAD(c + 1);
        COMPUTE();
        __syncthreads();
        if (c < 7) { STORE(); __syncthreads(); }
    }

#pragma unroll
    for (int mt = 0; mt < 4; mt++) {
        size_t roff = (m0 + m_base + mt*16) * DD;
#pragma unroll
        for (int nt = 0; nt < 2; nt++) {
            size_t off = roff + n0 + n_base + nt*16;
            if (resid) {
                FragC r;
                wmma::load_matrix_sync(r, resid + off, DD, wmma::mem_row_major);
#pragma unroll
                for (int e = 0; e < r.num_elements; e++) acc[mt][nt].x[e] += r.x[e];
            }
            wmma::store_matrix_sync(outp + off, acc[mt][nt], DD, wmma::mem_row_major);
        }
    }
}

// ---------------------------------------------------------------------------
// K4: mix — per (b,h): C[i, td] = sum_j attn[b,h,i,j] * v[b,j,td'],
//     td' = (t, h*32+d), td = t*32+d within this block's 128-wide td tile.
// attn = matrix_a (row_major, k=j); V staged [j][td] = matrix_b row_major.
// grid (32 td-blocks, 2 i-blocks, 64 bh), 256 thr; tile 128(i)x128(td)x32(j).
// ---------------------------------------------------------------------------
__global__ void __launch_bounds__(256) mixgemm_kernel() {
    __shared__ __align__(32) __nv_bfloat16 smem[2*5120 + 2*4352];
    __nv_bfloat16* Ph = smem;                   // attn hi: 128 x 40
    __nv_bfloat16* Pl = smem + 5120;            // attn lo
    __nv_bfloat16* Vh = smem + 10240;           // v hi: 32 j x 136
    __nv_bfloat16* Vl = smem + 14592;           // v lo

    const int tid = threadIdx.x, wid = tid >> 5;
    const int bh = blockIdx.z, b = bh >> 3, h = bh & 7;
    const int td0 = blockIdx.x * 128;
    const int i0 = blockIdx.y * 128;
    const int pr = tid >> 3, pk4 = (tid & 7) * 4;
    const int vj = tid >> 5, vtd = (tid & 31) * 4;
    const int m_base = (wid & 1) * 64;          // i
    const int n_base = (wid >> 1) * 32;         // td

    const float* Vb = g_v + (size_t)b * NN * TT * DD;
    const float* Pb = g_attn + (size_t)bh * NN * NN;

    FragC acc[4][2];
#pragma unroll
    for (int mt = 0; mt < 4; mt++)
#pragma unroll
        for (int nt = 0; nt < 2; nt++) wmma::fill_fragment(acc[mt][nt], 0.0f);

    float4 vreg[4], preg[4];
    auto LOAD = [&](int c) {
        int tdg = td0 + vtd;
        int ti = tdg >> 5, d = tdg & 31;
#pragma unroll
        for (int u = 0; u < 4; u++) {
            vreg[u] = *(const float4*)(Vb + ((size_t)(c*32 + vj + u*8)*TT + ti)*DD + h*32 + d);
            preg[u] = *(const float4*)(Pb + (size_t)(i0 + pr + u*32)*NN + c*32 + pk4);
        }
    };
    auto STORE = [&]() {
#pragma unroll
        for (int u = 0; u < 4; u++) {
            int poff = (pr + u*32)*40 + pk4;
            bf_split_store4(Ph + poff, Pl + poff, preg[u]);
            int voff = (vj + u*8)*136 + vtd;
            bf_split_store4(Vh + voff, Vl + voff, vreg[u]);
        }
    };
    auto COMPUTE = [&]() {
#pragma unroll
        for (int ks = 0; ks < 2; ks++) {
            FragA  af[4];
            FragBr bhf[2], blf[2];
#pragma unroll
            for (int mt = 0; mt < 4; mt++)
                wmma::load_matrix_sync(af[mt], Ph + (m_base + mt*16)*40 + ks*16, 40);
#pragma unroll
            for (int nt = 0; nt < 2; nt++) {
                wmma::load_matrix_sync(bhf[nt], Vh + ks*16*136 + n_base + nt*16, 136);
                wmma::load_matrix_sync(blf[nt], Vl + ks*16*136 + n_base + nt*16, 136);
            }
#pragma unroll
            for (int mt = 0; mt < 4; mt++)
#pragma unroll
                for (int nt = 0; nt < 2; nt++) {
                    wmma::mma_sync(acc[mt][nt], af[mt], bhf[nt], acc[mt][nt]);
                    wmma::mma_sync(acc[mt][nt], af[mt], blf[nt], acc[mt][nt]);
                }
#pragma unroll
            for (int mt = 0; mt < 4; mt++)
                wmma::load_matrix_sync(af[mt], Pl + (m_base + mt*16)*40 + ks*16, 40);
#pragma unroll
            for (int mt = 0; mt < 4; mt++)
#pragma unroll
                for (int nt = 0; nt < 2; nt++)
                    wmma::mma_sync(acc[mt][nt], af[mt], bhf[nt], acc[mt][nt]);
        }
    };

    LOAD(0);
    STORE();
    __syncthreads();
    for (int c = 0; c < 8; c++) {
        if (c < 7) LOAD(c + 1);
        COMPUTE();
        __syncthreads();
        if (c < 7) { STORE(); __syncthreads(); }
    }

#pragma unroll
    for (int mt = 0; mt < 4; mt++) {
        int irow0 = i0 + m_base + mt*16;
#pragma unroll
        for (int nt = 0; nt < 2; nt++) {
            int tdg0 = td0 + n_base + nt*16;
            int ti = tdg0 >> 5, d0 = tdg0 & 31;
            float* p = g_mixed + ((size_t)(b*NN + irow0)*TT + ti)*DD + h*32 + d0;
            wmma::store_matrix_sync(p, acc[mt][nt], TT*DD, wmma::mem_row_major);
        }
    }
}

// ---------------------------------------------------------------------------
extern "C" void kernel_launch(void* const* d_in, const int* in_sizes, int n_in,
                              void* d_out, int out_size) {
    const float* h_val = (const float*)d_in[0];
    const float* z_map = (const float*)d_in[1];
    const float* adj   = (const float*)d_in[2];
    const float* Wq    = (const float*)d_in[3];
    const float* Wk    = (const float*)d_in[4];
    const float* Wv    = (const float*)d_in[5];
    const float* Wo    = (const float*)d_in[6];

    float* out       = (float*)d_out;
    float* attn_mean = out + (size_t)BATCH*NN*TT*DD;
    float* raw_mean  = attn_mean + (size_t)BATCH*NN*NN;

    const int attn_smem = (64*257 + 256 + 256 + 8*256 + 8*256) * (int)sizeof(float);
    cudaFuncSetAttribute(attn_kernel, cudaFuncAttributeMaxDynamicSharedMemorySize, attn_smem);

    dim3 tgrid(8, 8, 2), tblk(32, 8);
    transpose_w_kernel<<<tgrid, tblk>>>(Wq, Wk);
    dim3 qkgrid(32, 2);
    gemm_qk_kernel<<<qkgrid, 256>>>(z_map);
    attn_kernel<<<BN, 256, attn_smem>>>(adj, attn_mean, raw_mean);
    dim3 wg((int)(M_BIG/128), 2);
    wgemm_kernel<<<wg, 256>>>(h_val, Wv, nullptr, nullptr, 0);
    dim3 gmix(32, 2, BATCH*HH);
    mixgemm_kernel<<<gmix, 256>>>();
    wgemm_kernel<<<wg, 256>>>(nullptr, Wo, out, h_val, 1);
}